// round 7
// baseline (speedup 1.0000x reference)
#include <cuda_runtime.h>
#include <cuda_bf16.h>
#include <cstdint>

// DeepSpeed fixed sparse self-attention, B=2, H=16, S=2048, D=64, fp32.
// q-rows [64t,64t+64) attend window keys [64t,64t+48) + stripes [64m+48,64m+64).
// Flash softmax; tile0 (window, 48 keys) peeled; tiles 1..8 = 4 stripes each.
// Math: mma.sync m16n8k16 bf16, 3-MMA split compensation (Ah*Bl + Al*Bh + Ah*Bh).
// R7: prepass splits K/V to bf16 hi/lo in gmem scratch; main kernel stages via
//     cp.async (double-buffered, 1 tile ahead), Q frags register-resident.

#define SEQ    2048
#define HD     64
#define NBH    32
#define NEGBIG (-1e30f)
#define SC2    0.18033688011112042f   // 0.125 * log2(e)
#define STAGEB 32768                  // bytes per stage: Kh,Kl,Vh,Vl * 8KB

// ---- device scratch: bf16 hi/lo of K and V, [bh][2048][64] ----
__device__ __align__(16) __nv_bfloat16 g_Kh[(size_t)NBH * SEQ * HD];
__device__ __align__(16) __nv_bfloat16 g_Kl[(size_t)NBH * SEQ * HD];
__device__ __align__(16) __nv_bfloat16 g_Vh[(size_t)NBH * SEQ * HD];
__device__ __align__(16) __nv_bfloat16 g_Vl[(size_t)NBH * SEQ * HD];

__device__ __forceinline__ void mma_bf16(float4& d,
                                         uint32_t a0, uint32_t a1, uint32_t a2, uint32_t a3,
                                         uint32_t b0, uint32_t b1)
{
    asm volatile(
        "mma.sync.aligned.m16n8k16.row.col.f32.bf16.bf16.f32 "
        "{%0,%1,%2,%3}, {%4,%5,%6,%7}, {%8,%9}, {%0,%1,%2,%3};\n"
        : "+f"(d.x), "+f"(d.y), "+f"(d.z), "+f"(d.w)
        : "r"(a0), "r"(a1), "r"(a2), "r"(a3), "r"(b0), "r"(b1));
}

__device__ __forceinline__ void ldsm_x4(uint32_t& r0, uint32_t& r1, uint32_t& r2, uint32_t& r3,
                                        uint32_t addr)
{
    asm volatile("ldmatrix.sync.aligned.m8n8.x4.shared.b16 {%0,%1,%2,%3}, [%4];"
                 : "=r"(r0), "=r"(r1), "=r"(r2), "=r"(r3) : "r"(addr));
}

__device__ __forceinline__ void ldsm_x2_t(uint32_t& r0, uint32_t& r1, uint32_t addr)
{
    asm volatile("ldmatrix.sync.aligned.m8n8.x2.trans.shared.b16 {%0,%1}, [%2];"
                 : "=r"(r0), "=r"(r1) : "r"(addr));
}

__device__ __forceinline__ void split2(float a, float b, uint32_t& h, uint32_t& l)
{
    __nv_bfloat162 hv = __floats2bfloat162_rn(a, b);
    h = *reinterpret_cast<uint32_t*>(&hv);
    float ra = a - __bfloat162float(hv.x);
    float rb = b - __bfloat162float(hv.y);
    __nv_bfloat162 lv = __floats2bfloat162_rn(ra, rb);
    l = *reinterpret_cast<uint32_t*>(&lv);
}

__device__ __forceinline__ void cp16(uint32_t dst, const void* src)
{
    asm volatile("cp.async.ca.shared.global [%0], [%1], 16;\n" :: "r"(dst), "l"(src));
}
__device__ __forceinline__ void cp_commit()
{
    asm volatile("cp.async.commit_group;\n" ::: "memory");
}
template<int N> __device__ __forceinline__ void cp_wait()
{
    asm volatile("cp.async.wait_group %0;\n" :: "n"(N) : "memory");
}

// ================= prepass: split K,V into bf16 hi/lo =================
__global__ void prepass_split(const float* __restrict__ K, const float* __restrict__ V, int n8)
{
    int i = blockIdx.x * blockDim.x + threadIdx.x;
    if (i >= n8) return;
    const float4* K4 = reinterpret_cast<const float4*>(K);
    const float4* V4 = reinterpret_cast<const float4*>(V);
    uint32_t h0, l0, h1, l1, h2, l2, h3, l3;

    float4 a = K4[2 * i], b = K4[2 * i + 1];
    split2(a.x, a.y, h0, l0); split2(a.z, a.w, h1, l1);
    split2(b.x, b.y, h2, l2); split2(b.z, b.w, h3, l3);
    reinterpret_cast<uint4*>(g_Kh)[i] = make_uint4(h0, h1, h2, h3);
    reinterpret_cast<uint4*>(g_Kl)[i] = make_uint4(l0, l1, l2, l3);

    a = V4[2 * i]; b = V4[2 * i + 1];
    split2(a.x, a.y, h0, l0); split2(a.z, a.w, h1, l1);
    split2(b.x, b.y, h2, l2); split2(b.z, b.w, h3, l3);
    reinterpret_cast<uint4*>(g_Vh)[i] = make_uint4(h0, h1, h2, h3);
    reinterpret_cast<uint4*>(g_Vl)[i] = make_uint4(l0, l1, l2, l3);
}

// ---- issue one tile's K/V staging (16 cp.async per thread) ----
__device__ __forceinline__ void stage_issue(uint32_t smb, int stage, int tile, int t,
                                            const __nv_bfloat16* kh, const __nv_bfloat16* kl,
                                            const __nv_bfloat16* vh, const __nv_bfloat16* vl,
                                            int tid)
{
    const int row = tid >> 1;
    const int c0  = (tid & 1) * 4;
    const int gk  = (tile == 0) ? (t * 64 + row)
                                : (((tile - 1) * 4 + (row >> 4)) * 64 + 48 + (row & 15));
    const size_t off = (size_t)gk * HD;
    const uint32_t drow = smb + stage * STAGEB + row * 128;
    #pragma unroll
    for (int c = 0; c < 4; c++) {
        const int ch = c0 + c;
        const uint32_t sw = (uint32_t)((ch ^ (row & 7)) << 4);
        cp16(drow + sw,          kh + off + ch * 8);
        cp16(drow + 8192 + sw,   kl + off + ch * 8);
        cp16(drow + 16384 + sw,  vh + off + ch * 8);
        cp16(drow + 24576 + sw,  vl + off + ch * 8);
    }
}

// ================= per-tile compute =================
// NTP: number of x4 K-fragment pairs (3 => 48 keys, 4 => 64 keys)
// KBPV: PV k-blocks of 16 keys. FIRST: initialize flash state.
template<int NTP, int KBPV, bool FIRST>
__device__ __forceinline__ void compute_tile(
    uint32_t sb, const uint32_t (&qh)[4][4], const uint32_t (&ql)[4][4],
    float4 (&o)[8], float& m0, float& m1, float& l0, float& l1, int lane)
{
    const int krow = (lane >> 4) * 8 + (lane & 7);
    const int kch  = (lane >> 3) & 1;
    const int vrow0 = lane & 15;

    float4 s[2 * NTP];
    #pragma unroll
    for (int i = 0; i < 2 * NTP; i++) s[i] = make_float4(0.f, 0.f, 0.f, 0.f);

    #pragma unroll
    for (int kb = 0; kb < 4; kb++) {
        #pragma unroll
        for (int ntp = 0; ntp < NTP; ntp++) {
            const int row = ntp * 16 + krow;
            const int ch  = kb * 2 + kch;
            const uint32_t a = sb + row * 128 + ((ch ^ (row & 7)) << 4);
            uint32_t bh0, bh1, bh2, bh3, bl0, bl1, bl2, bl3;
            ldsm_x4(bh0, bh1, bh2, bh3, a);
            ldsm_x4(bl0, bl1, bl2, bl3, a + 8192);
            mma_bf16(s[2 * ntp],     qh[kb][0], qh[kb][1], qh[kb][2], qh[kb][3], bl0, bl1);
            mma_bf16(s[2 * ntp],     ql[kb][0], ql[kb][1], ql[kb][2], ql[kb][3], bh0, bh1);
            mma_bf16(s[2 * ntp],     qh[kb][0], qh[kb][1], qh[kb][2], qh[kb][3], bh0, bh1);
            mma_bf16(s[2 * ntp + 1], qh[kb][0], qh[kb][1], qh[kb][2], qh[kb][3], bl2, bl3);
            mma_bf16(s[2 * ntp + 1], ql[kb][0], ql[kb][1], ql[kb][2], ql[kb][3], bh2, bh3);
            mma_bf16(s[2 * ntp + 1], qh[kb][0], qh[kb][1], qh[kb][2], qh[kb][3], bh2, bh3);
        }
    }

    // scale + streaming softmax (base-2)
    float rm0 = NEGBIG, rm1 = NEGBIG;
    #pragma unroll
    for (int nt = 0; nt < 2 * NTP; nt++) {
        s[nt].x *= SC2; s[nt].y *= SC2; s[nt].z *= SC2; s[nt].w *= SC2;
        rm0 = fmaxf(rm0, fmaxf(s[nt].x, s[nt].y));
        rm1 = fmaxf(rm1, fmaxf(s[nt].z, s[nt].w));
    }
    rm0 = fmaxf(rm0, __shfl_xor_sync(0xffffffffu, rm0, 1));
    rm0 = fmaxf(rm0, __shfl_xor_sync(0xffffffffu, rm0, 2));
    rm1 = fmaxf(rm1, __shfl_xor_sync(0xffffffffu, rm1, 1));
    rm1 = fmaxf(rm1, __shfl_xor_sync(0xffffffffu, rm1, 2));

    float mn0, mn1;
    if (FIRST) { mn0 = rm0; mn1 = rm1; }
    else       { mn0 = fmaxf(m0, rm0); mn1 = fmaxf(m1, rm1); }

    float rs0 = 0.f, rs1 = 0.f;
    #pragma unroll
    for (int nt = 0; nt < 2 * NTP; nt++) {
        s[nt].x = exp2f(s[nt].x - mn0);
        s[nt].y = exp2f(s[nt].y - mn0);
        s[nt].z = exp2f(s[nt].z - mn1);
        s[nt].w = exp2f(s[nt].w - mn1);
        rs0 += s[nt].x + s[nt].y;
        rs1 += s[nt].z + s[nt].w;
    }
    rs0 += __shfl_xor_sync(0xffffffffu, rs0, 1);
    rs0 += __shfl_xor_sync(0xffffffffu, rs0, 2);
    rs1 += __shfl_xor_sync(0xffffffffu, rs1, 1);
    rs1 += __shfl_xor_sync(0xffffffffu, rs1, 2);

    if (FIRST) {
        l0 = rs0; l1 = rs1; m0 = mn0; m1 = mn1;
    } else {
        const float alp0 = exp2f(m0 - mn0), alp1 = exp2f(m1 - mn1);
        m0 = mn0; m1 = mn1;
        l0 = l0 * alp0 + rs0;
        l1 = l1 * alp1 + rs1;
        #pragma unroll
        for (int dt = 0; dt < 8; dt++) {
            o[dt].x *= alp0; o[dt].y *= alp0;
            o[dt].z *= alp1; o[dt].w *= alp1;
        }
    }

    // O += P V
    #pragma unroll
    for (int kb = 0; kb < KBPV; kb++) {
        uint32_t ah0, al0_, ah1, al1_, ah2, al2_, ah3, al3_;
        split2(s[2 * kb].x,     s[2 * kb].y,     ah0, al0_);
        split2(s[2 * kb].z,     s[2 * kb].w,     ah1, al1_);
        split2(s[2 * kb + 1].x, s[2 * kb + 1].y, ah2, al2_);
        split2(s[2 * kb + 1].z, s[2 * kb + 1].w, ah3, al3_);
        const int row = kb * 16 + vrow0;
        #pragma unroll
        for (int dt = 0; dt < 8; dt++) {
            const uint32_t a = sb + 16384 + row * 128 + ((dt ^ (row & 7)) << 4);
            uint32_t bh0, bh1, bl0, bl1;
            ldsm_x2_t(bh0, bh1, a);
            ldsm_x2_t(bl0, bl1, a + 8192);
            mma_bf16(o[dt], ah0, ah1, ah2, ah3, bl0, bl1);
            mma_bf16(o[dt], al0_, al1_, al2_, al3_, bh0, bh1);
            mma_bf16(o[dt], ah0, ah1, ah2, ah3, bh0, bh1);
        }
    }
}

// ================= main kernel =================
__global__ void __launch_bounds__(128, 3)
sparse_attn_pipe(const float* __restrict__ Q, float* __restrict__ Out)
{
    extern __shared__ __align__(16) char smraw[];
    const uint32_t smb = (uint32_t)__cvta_generic_to_shared(smraw);

    const int tid  = threadIdx.x;
    const int warp = tid >> 5;
    const int lane = tid & 31;
    const int g    = lane >> 2;
    const int q4   = lane & 3;
    const int t    = blockIdx.x;
    const int bh   = blockIdx.y;

    const size_t base = (size_t)bh * SEQ * HD;
    const float* Qg = Q + base + (size_t)t * 64 * HD;
    float*       Og = Out + base + (size_t)t * 64 * HD;
    const __nv_bfloat16* khp = g_Kh + base;
    const __nv_bfloat16* klp = g_Kl + base;
    const __nv_bfloat16* vhp = g_Vh + base;
    const __nv_bfloat16* vlp = g_Vl + base;

    // G0: tile0 -> stage0 (overlaps with Q staging below)
    stage_issue(smb, 0, 0, t, khp, klp, vhp, vlp, tid);
    cp_commit();

    // ---- stage Q hi/lo into stage1's K area (temp), then load frags to regs ----
    #pragma unroll
    for (int it = 0; it < 4; it++) {
        int idx = tid + it * 128;             // 0..511
        int r = idx >> 3, ch = idx & 7;
        const float4* src = reinterpret_cast<const float4*>(Qg + r * HD + ch * 8);
        float4 a = src[0], b = src[1];
        uint32_t h0, l0_, h1, l1_, h2, l2_, h3, l3_;
        split2(a.x, a.y, h0, l0_); split2(a.z, a.w, h1, l1_);
        split2(b.x, b.y, h2, l2_); split2(b.z, b.w, h3, l3_);
        const uint32_t sw = (uint32_t)((ch ^ (r & 7)) << 4);
        *reinterpret_cast<uint4*>(smraw + STAGEB + r * 128 + sw)        = make_uint4(h0, h1, h2, h3);
        *reinterpret_cast<uint4*>(smraw + STAGEB + 8192 + r * 128 + sw) = make_uint4(l0_, l1_, l2_, l3_);
    }
    __syncthreads();

    uint32_t qh[4][4], ql[4][4];
    {
        const int qrow = warp * 16 + ((lane >> 3) & 1) * 8 + (lane & 7);
        #pragma unroll
        for (int kb = 0; kb < 4; kb++) {
            const int ch = kb * 2 + (lane >> 4);
            const uint32_t a = smb + STAGEB + qrow * 128 + ((ch ^ (qrow & 7)) << 4);
            ldsm_x4(qh[kb][0], qh[kb][1], qh[kb][2], qh[kb][3], a);
            ldsm_x4(ql[kb][0], ql[kb][1], ql[kb][2], ql[kb][3], a + 8192);
        }
    }
    __syncthreads();   // stage1 free for tile1 staging

    // G1: tile1 -> stage1
    stage_issue(smb, 1, 1, t, khp, klp, vhp, vlp, tid);
    cp_commit();

    float4 o[8];
    #pragma unroll
    for (int i = 0; i < 8; i++) o[i] = make_float4(0.f, 0.f, 0.f, 0.f);
    float m0 = 0.f, m1 = 0.f, l0 = 0.f, l1 = 0.f;
    const int r0 = warp * 16 + g;

    // ---- tile 0 (window, 48 valid keys) ----
    cp_wait<1>();
    __syncthreads();
    compute_tile<3, 3, true>(smb, qh, ql, o, m0, m1, l0, l1, lane);
    __syncthreads();
    stage_issue(smb, 0, 2, t, khp, klp, vhp, vlp, tid);   // G2: tile2 -> stage0
    cp_commit();

    // ---- tiles 1..8 (stripes) ----
    for (int tile = 1; tile < 9; tile++) {
        if (tile < 8) cp_wait<1>(); else cp_wait<0>();
        __syncthreads();
        compute_tile<4, 4, false>(smb + (uint32_t)(tile & 1) * STAGEB,
                                  qh, ql, o, m0, m1, l0, l1, lane);
        __syncthreads();
        if (tile + 2 <= 8)
            stage_issue(smb, tile & 1, tile + 2, t, khp, klp, vhp, vlp, tid);
        cp_commit();   // commit even when empty to keep group accounting simple
    }

    // ---- epilogue ----
    const float inv0 = 1.f / l0, inv1 = 1.f / l1;
    #pragma unroll
    for (int dt = 0; dt < 8; dt++) {
        *reinterpret_cast<float2*>(Og + r0 * HD + dt * 8 + 2 * q4) =
            make_float2(o[dt].x * inv0, o[dt].y * inv0);
        *reinterpret_cast<float2*>(Og + (r0 + 8) * HD + dt * 8 + 2 * q4) =
            make_float2(o[dt].z * inv1, o[dt].w * inv1);
    }
}

extern "C" void kernel_launch(void* const* d_in, const int* in_sizes, int n_in,
                              void* d_out, int out_size)
{
    const float* Q = (const float*)d_in[0];
    const float* K = (const float*)d_in[1];
    const float* V = (const float*)d_in[2];
    float* O = (float*)d_out;

    const int nbh = in_sizes[0] / (SEQ * HD);      // 32
    const int n8  = nbh * SEQ * HD / 8;
    prepass_split<<<(n8 + 255) / 256, 256>>>(K, V, n8);

    const int smem = 2 * STAGEB;                    // 65536 B
    cudaFuncSetAttribute(sparse_attn_pipe,
                         cudaFuncAttributeMaxDynamicSharedMemorySize, smem);
    dim3 grid(SEQ / 64, nbh);
    sparse_attn_pipe<<<grid, 128, smem>>>(Q, O);
}

// round 8
// speedup vs baseline: 1.1932x; 1.1932x over previous
#include <cuda_runtime.h>
#include <cuda_bf16.h>
#include <cstdint>

// DeepSpeed fixed sparse self-attention, B=2, H=16, S=2048, D=64, fp32.
// q-rows [64t,64t+64) attend window keys [64t,64t+48) + stripes [64m+48,64m+64).
// Flash softmax; tile0 (window, 48 keys) peeled; tiles 1..8 = 4 stripes each.
// Math: mma.sync m16n8k16 bf16, 3-MMA split compensation (Ah*Bl + Al*Bh + Ah*Bh).
// R8: prepass pre-splits K/V to bf16 hi/lo in gmem; R6's synchronous 4-CTA/SM
//     skeleton; staging is lean LDG.128+STS.128; XOR-swizzled 128B rows;
//     V fragments via ldmatrix.x4.trans.

#define SEQ    2048
#define HD     64
#define NBH    32
#define NEGBIG (-1e30f)
#define SC2    0.18033688011112042f   // 0.125 * log2(e)

// smem byte offsets (128B per row, 64 rows per array)
#define SM_QH  0
#define SM_QL  8192
#define SM_KH  16384
#define SM_KL  24576
#define SM_VH  32768
#define SM_VL  40960
#define SM_TOT 49152

// ---- device scratch: bf16 hi/lo of K and V, [bh][2048][64] ----
__device__ __align__(16) __nv_bfloat16 g_Kh[(size_t)NBH * SEQ * HD];
__device__ __align__(16) __nv_bfloat16 g_Kl[(size_t)NBH * SEQ * HD];
__device__ __align__(16) __nv_bfloat16 g_Vh[(size_t)NBH * SEQ * HD];
__device__ __align__(16) __nv_bfloat16 g_Vl[(size_t)NBH * SEQ * HD];

__device__ __forceinline__ void mma_bf16(float4& d,
                                         uint32_t a0, uint32_t a1, uint32_t a2, uint32_t a3,
                                         uint32_t b0, uint32_t b1)
{
    asm volatile(
        "mma.sync.aligned.m16n8k16.row.col.f32.bf16.bf16.f32 "
        "{%0,%1,%2,%3}, {%4,%5,%6,%7}, {%8,%9}, {%0,%1,%2,%3};\n"
        : "+f"(d.x), "+f"(d.y), "+f"(d.z), "+f"(d.w)
        : "r"(a0), "r"(a1), "r"(a2), "r"(a3), "r"(b0), "r"(b1));
}

__device__ __forceinline__ void ldsm_x4(uint32_t& r0, uint32_t& r1, uint32_t& r2, uint32_t& r3,
                                        uint32_t addr)
{
    asm volatile("ldmatrix.sync.aligned.m8n8.x4.shared.b16 {%0,%1,%2,%3}, [%4];"
                 : "=r"(r0), "=r"(r1), "=r"(r2), "=r"(r3) : "r"(addr));
}

__device__ __forceinline__ void ldsm_x4_t(uint32_t& r0, uint32_t& r1, uint32_t& r2, uint32_t& r3,
                                          uint32_t addr)
{
    asm volatile("ldmatrix.sync.aligned.m8n8.x4.trans.shared.b16 {%0,%1,%2,%3}, [%4];"
                 : "=r"(r0), "=r"(r1), "=r"(r2), "=r"(r3) : "r"(addr));
}

__device__ __forceinline__ void split2(float a, float b, uint32_t& h, uint32_t& l)
{
    __nv_bfloat162 hv = __floats2bfloat162_rn(a, b);
    h = *reinterpret_cast<uint32_t*>(&hv);
    float ra = a - __bfloat162float(hv.x);
    float rb = b - __bfloat162float(hv.y);
    __nv_bfloat162 lv = __floats2bfloat162_rn(ra, rb);
    l = *reinterpret_cast<uint32_t*>(&lv);
}

// ================= prepass: split K,V into bf16 hi/lo =================
__global__ void prepass_split(const float* __restrict__ K, const float* __restrict__ V, int n8)
{
    int i = blockIdx.x * blockDim.x + threadIdx.x;
    if (i >= n8) return;
    const float4* K4 = reinterpret_cast<const float4*>(K);
    const float4* V4 = reinterpret_cast<const float4*>(V);
    uint32_t h0, l0, h1, l1, h2, l2, h3, l3;

    float4 a = K4[2 * i], b = K4[2 * i + 1];
    split2(a.x, a.y, h0, l0); split2(a.z, a.w, h1, l1);
    split2(b.x, b.y, h2, l2); split2(b.z, b.w, h3, l3);
    reinterpret_cast<uint4*>(g_Kh)[i] = make_uint4(h0, h1, h2, h3);
    reinterpret_cast<uint4*>(g_Kl)[i] = make_uint4(l0, l1, l2, l3);

    a = V4[2 * i]; b = V4[2 * i + 1];
    split2(a.x, a.y, h0, l0); split2(a.z, a.w, h1, l1);
    split2(b.x, b.y, h2, l2); split2(b.z, b.w, h3, l3);
    reinterpret_cast<uint4*>(g_Vh)[i] = make_uint4(h0, h1, h2, h3);
    reinterpret_cast<uint4*>(g_Vl)[i] = make_uint4(l0, l1, l2, l3);
}

// ---- stage one tile's K/V: 16 x (LDG.128 + STS.128) per thread ----
__device__ __forceinline__ void stage_kv(char* sm, int tile, int t,
                                         const uint4* kh, const uint4* kl,
                                         const uint4* vh, const uint4* vl, int tid)
{
    #pragma unroll
    for (int it = 0; it < 4; it++) {
        int idx = tid + it * 128;                 // 0..511
        int row = idx >> 3, ch = idx & 7;
        int gk = (tile == 0) ? (t * 64 + row)
                             : (((tile - 1) * 4 + (row >> 4)) * 64 + 48 + (row & 15));
        size_t goff = (size_t)gk * 8 + ch;
        uint32_t sw = (uint32_t)(row * 128 + ((ch ^ (row & 7)) << 4));
        *reinterpret_cast<uint4*>(sm + SM_KH + sw) = kh[goff];
        *reinterpret_cast<uint4*>(sm + SM_KL + sw) = kl[goff];
        *reinterpret_cast<uint4*>(sm + SM_VH + sw) = vh[goff];
        *reinterpret_cast<uint4*>(sm + SM_VL + sw) = vl[goff];
    }
}

// ================= per-tile compute =================
// NTP: x4 K-fragment pairs (3 => 48 keys, 4 => 64 keys); KBPV: PV 16-key blocks.
template<int NTP, int KBPV, bool FIRST>
__device__ __forceinline__ void compute_tile(
    uint32_t smb, float4 (&o)[8],
    float& m0, float& m1, float& l0, float& l1, int lane, int warp)
{
    // per-lane fragment geometry
    const int arow  = (warp << 4) + (((lane >> 3) & 1) << 3) + (lane & 7);  // Q rows
    const int krow0 = ((lane >> 4) << 3) + (lane & 7);                       // K rows base
    const int kchp  = (lane >> 3) & 1;
    const int vrow0 = (((lane >> 3) & 1) << 3) + (lane & 7);                 // V rows base
    const int vchp  = lane >> 4;

    float4 s[2 * NTP];
    #pragma unroll
    for (int i = 0; i < 2 * NTP; i++) s[i] = make_float4(0.f, 0.f, 0.f, 0.f);

    #pragma unroll
    for (int kb = 0; kb < 4; kb++) {
        const int qch = kb * 2 + (lane >> 4);
        const uint32_t qa = smb + SM_QH + arow * 128 + ((qch ^ (arow & 7)) << 4);
        uint32_t ah0, ah1, ah2, ah3, al0, al1, al2, al3;
        ldsm_x4(ah0, ah1, ah2, ah3, qa);
        ldsm_x4(al0, al1, al2, al3, qa + (SM_QL - SM_QH));
        #pragma unroll
        for (int ntp = 0; ntp < NTP; ntp++) {
            const int krow = ntp * 16 + krow0;
            const int kch  = kb * 2 + kchp;
            const uint32_t ka = smb + SM_KH + krow * 128 + ((kch ^ (krow & 7)) << 4);
            uint32_t bh0, bh1, bh2, bh3, bl0, bl1, bl2, bl3;
            ldsm_x4(bh0, bh1, bh2, bh3, ka);
            ldsm_x4(bl0, bl1, bl2, bl3, ka + (SM_KL - SM_KH));
            mma_bf16(s[2 * ntp],     ah0, ah1, ah2, ah3, bl0, bl1);
            mma_bf16(s[2 * ntp],     al0, al1, al2, al3, bh0, bh1);
            mma_bf16(s[2 * ntp],     ah0, ah1, ah2, ah3, bh0, bh1);
            mma_bf16(s[2 * ntp + 1], ah0, ah1, ah2, ah3, bl2, bl3);
            mma_bf16(s[2 * ntp + 1], al0, al1, al2, al3, bh2, bh3);
            mma_bf16(s[2 * ntp + 1], ah0, ah1, ah2, ah3, bh2, bh3);
        }
    }

    // scale + streaming softmax (base-2)
    float rm0 = NEGBIG, rm1 = NEGBIG;
    #pragma unroll
    for (int nt = 0; nt < 2 * NTP; nt++) {
        s[nt].x *= SC2; s[nt].y *= SC2; s[nt].z *= SC2; s[nt].w *= SC2;
        rm0 = fmaxf(rm0, fmaxf(s[nt].x, s[nt].y));
        rm1 = fmaxf(rm1, fmaxf(s[nt].z, s[nt].w));
    }
    rm0 = fmaxf(rm0, __shfl_xor_sync(0xffffffffu, rm0, 1));
    rm0 = fmaxf(rm0, __shfl_xor_sync(0xffffffffu, rm0, 2));
    rm1 = fmaxf(rm1, __shfl_xor_sync(0xffffffffu, rm1, 1));
    rm1 = fmaxf(rm1, __shfl_xor_sync(0xffffffffu, rm1, 2));

    float mn0, mn1;
    if (FIRST) { mn0 = rm0; mn1 = rm1; }
    else       { mn0 = fmaxf(m0, rm0); mn1 = fmaxf(m1, rm1); }

    float rs0 = 0.f, rs1 = 0.f;
    #pragma unroll
    for (int nt = 0; nt < 2 * NTP; nt++) {
        s[nt].x = exp2f(s[nt].x - mn0);
        s[nt].y = exp2f(s[nt].y - mn0);
        s[nt].z = exp2f(s[nt].z - mn1);
        s[nt].w = exp2f(s[nt].w - mn1);
        rs0 += s[nt].x + s[nt].y;
        rs1 += s[nt].z + s[nt].w;
    }
    rs0 += __shfl_xor_sync(0xffffffffu, rs0, 1);
    rs0 += __shfl_xor_sync(0xffffffffu, rs0, 2);
    rs1 += __shfl_xor_sync(0xffffffffu, rs1, 1);
    rs1 += __shfl_xor_sync(0xffffffffu, rs1, 2);

    if (FIRST) {
        l0 = rs0; l1 = rs1; m0 = mn0; m1 = mn1;
    } else {
        const float alp0 = exp2f(m0 - mn0), alp1 = exp2f(m1 - mn1);
        m0 = mn0; m1 = mn1;
        l0 = l0 * alp0 + rs0;
        l1 = l1 * alp1 + rs1;
        #pragma unroll
        for (int dt = 0; dt < 8; dt++) {
            o[dt].x *= alp0; o[dt].y *= alp0;
            o[dt].z *= alp1; o[dt].w *= alp1;
        }
    }

    // O += P V : V B-frags via ldmatrix.x4.trans (2 d-tiles per load)
    #pragma unroll
    for (int kb = 0; kb < KBPV; kb++) {
        uint32_t ah0, al0_, ah1, al1_, ah2, al2_, ah3, al3_;
        split2(s[2 * kb].x,     s[2 * kb].y,     ah0, al0_);
        split2(s[2 * kb].z,     s[2 * kb].w,     ah1, al1_);
        split2(s[2 * kb + 1].x, s[2 * kb + 1].y, ah2, al2_);
        split2(s[2 * kb + 1].z, s[2 * kb + 1].w, ah3, al3_);
        const int vrow = kb * 16 + vrow0;
        #pragma unroll
        for (int dtp = 0; dtp < 4; dtp++) {
            const int vch = dtp * 2 + vchp;
            const uint32_t va = smb + SM_VH + vrow * 128 + ((vch ^ (vrow & 7)) << 4);
            uint32_t bh0, bh1, bh2, bh3, bl0, bl1, bl2, bl3;
            ldsm_x4_t(bh0, bh1, bh2, bh3, va);
            ldsm_x4_t(bl0, bl1, bl2, bl3, va + (SM_VL - SM_VH));
            mma_bf16(o[2 * dtp],     ah0, ah1, ah2, ah3, bl0, bl1);
            mma_bf16(o[2 * dtp],     al0_, al1_, al2_, al3_, bh0, bh1);
            mma_bf16(o[2 * dtp],     ah0, ah1, ah2, ah3, bh0, bh1);
            mma_bf16(o[2 * dtp + 1], ah0, ah1, ah2, ah3, bl2, bl3);
            mma_bf16(o[2 * dtp + 1], al0_, al1_, al2_, al3_, bh2, bh3);
            mma_bf16(o[2 * dtp + 1], ah0, ah1, ah2, ah3, bh2, bh3);
        }
    }
}

// ================= main kernel =================
__global__ void __launch_bounds__(128, 4)
sparse_attn_bf16(const float* __restrict__ Q, float* __restrict__ Out)
{
    extern __shared__ __align__(16) char smraw[];
    const uint32_t smb = (uint32_t)__cvta_generic_to_shared(smraw);

    const int tid  = threadIdx.x;
    const int warp = tid >> 5;
    const int lane = tid & 31;
    const int g    = lane >> 2;
    const int q4   = lane & 3;
    const int t    = blockIdx.x;
    const int bh   = blockIdx.y;

    const size_t base = (size_t)bh * SEQ * HD;
    const float* Qg = Q + base + (size_t)t * 64 * HD;
    float*       Og = Out + base + (size_t)t * 64 * HD;
    const uint4* khp = reinterpret_cast<const uint4*>(g_Kh + base);
    const uint4* klp = reinterpret_cast<const uint4*>(g_Kl + base);
    const uint4* vhp = reinterpret_cast<const uint4*>(g_Vh + base);
    const uint4* vlp = reinterpret_cast<const uint4*>(g_Vl + base);

    // ---- stage Q hi/lo (once) into swizzled layout ----
    #pragma unroll
    for (int it = 0; it < 4; it++) {
        int idx = tid + it * 128;             // 0..511
        int r = idx >> 3, ch = idx & 7;
        const float4* src = reinterpret_cast<const float4*>(Qg + r * HD + ch * 8);
        float4 a = src[0], b = src[1];
        uint32_t h0, l0_, h1, l1_, h2, l2_, h3, l3_;
        split2(a.x, a.y, h0, l0_); split2(a.z, a.w, h1, l1_);
        split2(b.x, b.y, h2, l2_); split2(b.z, b.w, h3, l3_);
        const uint32_t sw = (uint32_t)(r * 128 + ((ch ^ (r & 7)) << 4));
        *reinterpret_cast<uint4*>(smraw + SM_QH + sw) = make_uint4(h0, h1, h2, h3);
        *reinterpret_cast<uint4*>(smraw + SM_QL + sw) = make_uint4(l0_, l1_, l2_, l3_);
    }

    float4 o[8];
    #pragma unroll
    for (int i = 0; i < 8; i++) o[i] = make_float4(0.f, 0.f, 0.f, 0.f);
    float m0 = 0.f, m1 = 0.f, l0 = 0.f, l1 = 0.f;
    const int r0 = warp * 16 + g;

    // ---- tile 0: window (48 valid keys) ----
    stage_kv(smraw, 0, t, khp, klp, vhp, vlp, tid);
    __syncthreads();
    compute_tile<3, 3, true>(smb, o, m0, m1, l0, l1, lane, warp);

    // ---- tiles 1..8: stripes ----
    for (int tile = 1; tile < 9; tile++) {
        __syncthreads();   // all warps done reading previous K/V
        stage_kv(smraw, tile, t, khp, klp, vhp, vlp, tid);
        __syncthreads();
        compute_tile<4, 4, false>(smb, o, m0, m1, l0, l1, lane, warp);
    }

    // ---- epilogue ----
    const float inv0 = 1.f / l0, inv1 = 1.f / l1;
    #pragma unroll
    for (int dt = 0; dt < 8; dt++) {
        *reinterpret_cast<float2*>(Og + r0 * HD + dt * 8 + 2 * q4) =
            make_float2(o[dt].x * inv0, o[dt].y * inv0);
        *reinterpret_cast<float2*>(Og + (r0 + 8) * HD + dt * 8 + 2 * q4) =
            make_float2(o[dt].z * inv1, o[dt].w * inv1);
    }
}

extern "C" void kernel_launch(void* const* d_in, const int* in_sizes, int n_in,
                              void* d_out, int out_size)
{
    const float* Q = (const float*)d_in[0];
    const float* K = (const float*)d_in[1];
    const float* V = (const float*)d_in[2];
    float* O = (float*)d_out;

    const int nbh = in_sizes[0] / (SEQ * HD);      // 32
    const int n8  = nbh * SEQ * HD / 8;
    prepass_split<<<(n8 + 255) / 256, 256>>>(K, V, n8);

    cudaFuncSetAttribute(sparse_attn_bf16,
                         cudaFuncAttributeMaxDynamicSharedMemorySize, SM_TOT);
    dim3 grid(SEQ / 64, nbh);
    sparse_attn_bf16<<<grid, 128, SM_TOT>>>(Q, O);
}